// round 6
// baseline (speedup 1.0000x reference)
#include <cuda_runtime.h>
#include <cuda_fp16.h>
#include <cstdint>

#define B_ROWS 65536
#define D_IN   784
#define KP     800      // K padded to 25 slabs of 32
#define D_H    300
#define DHP    304      // padded h width (stride)
#define BNP    304      // padded binarized-W1 rows (2 x 152 per warp-col)
#define D_OUT  10
#define EPSV   1e-5f
#define G1_BLOCKS (B_ROWS / 128)   // 512
#define G2_BLOCKS (B_ROWS / 128)   // 512
#define NSLAB  25

// ---------------- scratch ---------------------------------------------------
__device__ __align__(16) __half g_Bh1[BNP * KP];            // sign(W1) fp16, zero-padded
__device__ __align__(16) __half g_B2h[16 * DHP];            // sign(W2) -> later S' = sign(W2) * a
__device__ __align__(16) __half g_h[(size_t)B_ROWS * DHP];  // layer-1 pre-BN output
__device__ __align__(16) float  g_part1s[DHP * G1_BLOCKS];
__device__ __align__(16) float  g_part1q[DHP * G1_BLOCKS];
__device__ __align__(16) float  g_ab1[2 * DHP];
__device__ __align__(16) float  g_c2[16];                   // c = S @ b  (cols >=10 zero)
__device__ __align__(16) float  g_part2[G2_BLOCKS * 20];
__device__ __align__(16) float  g_ab2[2 * D_OUT];

__device__ __forceinline__ uint32_t smem_u32(const void* p) {
    uint32_t a;
    asm("{ .reg .u64 t; cvta.to.shared.u64 t, %1; cvt.u32.u64 %0, t; }" : "=r"(a) : "l"(p));
    return a;
}

#define MMA16816(acc, a0,a1,a2,a3, b0,b1)                                      \
    asm volatile(                                                              \
        "mma.sync.aligned.m16n8k16.row.col.f32.f16.f16.f32 "                   \
        "{%0,%1,%2,%3}, {%4,%5,%6,%7}, {%8,%9}, {%0,%1,%2,%3};\n"              \
        : "+f"(acc[0]), "+f"(acc[1]), "+f"(acc[2]), "+f"(acc[3])               \
        : "r"(a0), "r"(a1), "r"(a2), "r"(a3), "r"(b0), "r"(b1))

#define LDSM_X4(r0,r1,r2,r3, addr)                                             \
    asm volatile("ldmatrix.sync.aligned.m8n8.x4.shared.b16 {%0,%1,%2,%3}, [%4];" \
        : "=r"(r0), "=r"(r1), "=r"(r2), "=r"(r3) : "r"(addr))

#define LDSM_X2(r0,r1, addr)                                                   \
    asm volatile("ldmatrix.sync.aligned.m8n8.x2.shared.b16 {%0,%1}, [%2];"     \
        : "=r"(r0), "=r"(r1) : "r"(addr))

#define CP_ASYNC16(dst, src)                                                   \
    asm volatile("cp.async.cg.shared.global [%0], [%1], 16;"                   \
        :: "r"(dst), "l"(src) : "memory")
#define CP_COMMIT() asm volatile("cp.async.commit_group;" ::: "memory")
#define CP_WAIT2()  asm volatile("cp.async.wait_group 2;" ::: "memory")

// ---------------- prep: binarize weights ----------------------------------
__global__ void prep_kernel(const float* __restrict__ W1, const float* __restrict__ W2) {
    int i = blockIdx.x * blockDim.x + threadIdx.x;
    const int n1 = BNP * KP;
    if (i < n1) {
        int n = i / KP, k = i - n * KP;
        float v = 0.f;
        if (n < D_H && k < D_IN) v = (W1[n * D_IN + k] >= 0.f) ? 1.f : -1.f;
        g_Bh1[i] = __float2half_rn(v);
    } else {
        int j = i - n1;
        if (j < 16 * DHP) {
            int r = j / DHP, c = j - r * DHP;
            float v = 0.f;
            if (r < D_OUT && c < D_H) v = (W2[r * D_H + c] >= 0.f) ? 1.f : -1.f;
            g_B2h[j] = __float2half_rn(v);
        }
    }
}

// ---------------- GEMM1: h = x @ sign(W1)^T + fused BN1 partials ----------
// 128x304 tile, BK=32 double-buffered, 512 threads (16 warps: 8m x 2n).
// Warp tile 16x152 -> 19 n8 mmas per k16 (9 LDSM.x4 + 1 LDSM.x2 for B).
// Row stride 80B (LDSM conflict-free: r*20 mod 32 distinct for r=0..7).
//
// dyn smem (bytes): A0 @0 (10240), A1 @10240, B0 @20480 (304*80=24320), B1 @44800
#define SMEM1_TOTAL (20480 + 2 * 24320)

__global__ __launch_bounds__(512, 1) void gemm1_kernel(const float* __restrict__ x) {
    extern __shared__ __align__(128) char smem[];
    const uint32_t sb = smem_u32(smem);
    const int tid  = threadIdx.x;
    const int wid  = tid >> 5, lane = tid & 31;
    const int wm   = wid >> 1, wn   = wid & 1;
    const int g    = lane >> 2, tg  = lane & 3;
    const int m0   = blockIdx.x * 128;

    float acc[19][4];
#pragma unroll
    for (int nt = 0; nt < 19; nt++)
#pragma unroll
        for (int e = 0; e < 4; e++) acc[nt][e] = 0.f;

    const uint32_t aAddr = sb + (uint32_t)((wm * 16 + (lane & 15)) * 80 + (lane >> 4) * 16);
    const uint32_t bAddrX4 = sb + 20480u
        + (uint32_t)((wn * 152 + (lane & 7) + ((lane >> 4) << 3)) * 80 + ((lane >> 3) & 1) * 16);
    const uint32_t bAddrX2 = sb + 20480u
        + (uint32_t)((wn * 152 + 144 + (lane & 7)) * 80 + ((lane >> 3) & 1) * 16);

    const float* xBase = x + (size_t)m0 * D_IN;
    float4 aR[2];
    uint4  bR[3];

    // B slab = 304 rows x 32 halves = 1216 uint4: u -> (row=u>>2, quad=u&3)
#define LDG_SLAB(S)                                                              \
    do {                                                                         \
        const int kb = (S) * 32;                                                 \
        _Pragma("unroll")                                                        \
        for (int j = 0; j < 2; j++) {                                            \
            const int e = tid + 512 * j, row = e >> 3, c4 = (e & 7) * 4;         \
            aR[j] = (kb + c4 < D_IN)                                             \
                ? *(const float4*)(xBase + (size_t)row * D_IN + kb + c4)         \
                : make_float4(0.f, 0.f, 0.f, 0.f);                               \
        }                                                                        \
        _Pragma("unroll")                                                        \
        for (int j = 0; j < 2; j++) {                                            \
            const int u = tid + 512 * j;                                         \
            if (u < 1216)                                                        \
                bR[j] = *(const uint4*)(g_Bh1 + (size_t)(u >> 2) * KP + kb + (u & 3) * 8); \
        }                                                                        \
        if (tid < 192) {                                                         \
            const int u = 1024 + tid;                                            \
            bR[2] = *(const uint4*)(g_Bh1 + (size_t)(u >> 2) * KP + kb + (u & 3) * 8); \
        }                                                                        \
    } while (0)

#define STS_SLAB(BUF)                                                            \
    do {                                                                         \
        const uint32_t aoff = (BUF) * 10240u;                                    \
        const uint32_t boff = 20480u + (BUF) * 24320u;                           \
        _Pragma("unroll")                                                        \
        for (int j = 0; j < 2; j++) {                                            \
            const int e = tid + 512 * j, row = e >> 3, c4 = (e & 7) * 4;         \
            __half2 h0 = __floats2half2_rn(aR[j].x, aR[j].y);                    \
            __half2 h1 = __floats2half2_rn(aR[j].z, aR[j].w);                    \
            uint2 v;                                                             \
            v.x = *(uint32_t*)&h0; v.y = *(uint32_t*)&h1;                        \
            *(uint2*)(smem + aoff + row * 80 + c4 * 2) = v;                      \
        }                                                                        \
        _Pragma("unroll")                                                        \
        for (int j = 0; j < 2; j++) {                                            \
            const int u = tid + 512 * j;                                         \
            if (u < 1216)                                                        \
                *(uint4*)(smem + boff + (u >> 2) * 80 + (u & 3) * 16) = bR[j];   \
        }                                                                        \
        if (tid < 192) {                                                         \
            const int u = 1024 + tid;                                            \
            *(uint4*)(smem + boff + (u >> 2) * 80 + (u & 3) * 16) = bR[2];       \
        }                                                                        \
    } while (0)

#define COMPUTE_SLAB(BUF)                                                        \
    do {                                                                         \
        const uint32_t ab  = aAddr   + (BUF) * 10240u;                           \
        const uint32_t bb4 = bAddrX4 + (BUF) * 24320u;                           \
        const uint32_t bb2 = bAddrX2 + (BUF) * 24320u;                           \
        _Pragma("unroll")                                                        \
        for (int kk = 0; kk < 2; kk++) {                                         \
            uint32_t a0, a1, a2, a3;                                             \
            LDSM_X4(a0, a1, a2, a3, ab + kk * 32);                               \
            _Pragma("unroll")                                                    \
            for (int p = 0; p < 9; p++) {                                        \
                uint32_t b0, b1, b2, b3;                                         \
                LDSM_X4(b0, b1, b2, b3, bb4 + p * 1280 + kk * 32);               \
                MMA16816(acc[2 * p],     a0, a1, a2, a3, b0, b1);                \
                MMA16816(acc[2 * p + 1], a0, a1, a2, a3, b2, b3);                \
            }                                                                    \
            {                                                                    \
                uint32_t b0, b1;                                                 \
                LDSM_X2(b0, b1, bb2 + kk * 32);                                  \
                MMA16816(acc[18], a0, a1, a2, a3, b0, b1);                       \
            }                                                                    \
        }                                                                        \
    } while (0)

    LDG_SLAB(0);
    STS_SLAB(0);
    __syncthreads();
    for (int s = 0; s < NSLAB; s++) {
        const int buf = s & 1;
        if (s < NSLAB - 1) LDG_SLAB(s + 1);
        COMPUTE_SLAB(buf);
        if (s < NSLAB - 1) STS_SLAB(buf ^ 1);
        __syncthreads();
    }
#undef LDG_SLAB
#undef STS_SLAB
#undef COMPUTE_SLAB

    // h stores (fp16), all 304 cols valid
    const int row0 = m0 + wm * 16 + g;
#pragma unroll
    for (int nt = 0; nt < 19; nt++) {
        const int col = wn * 152 + nt * 8 + tg * 2;
        *(__half2*)&g_h[(size_t)row0 * DHP + col]       = __floats2half2_rn(acc[nt][0], acc[nt][1]);
        *(__half2*)&g_h[(size_t)(row0 + 8) * DHP + col] = __floats2half2_rn(acc[nt][2], acc[nt][3]);
    }

    // fused BN1 column partials (deterministic): sp sums [8][304], squares at +2432
    float* sp = (float*)smem;
#pragma unroll
    for (int nt = 0; nt < 19; nt++) {
        float s0 = acc[nt][0] + acc[nt][2];
        float s1 = acc[nt][1] + acc[nt][3];
        float q0 = acc[nt][0] * acc[nt][0] + acc[nt][2] * acc[nt][2];
        float q1 = acc[nt][1] * acc[nt][1] + acc[nt][3] * acc[nt][3];
#pragma unroll
        for (int o = 4; o < 32; o <<= 1) {
            s0 += __shfl_xor_sync(0xffffffffu, s0, o);
            s1 += __shfl_xor_sync(0xffffffffu, s1, o);
            q0 += __shfl_xor_sync(0xffffffffu, q0, o);
            q1 += __shfl_xor_sync(0xffffffffu, q1, o);
        }
        if (lane < 4) {
            const int col = wn * 152 + nt * 8 + tg * 2;
            sp[wm * 304 + col]            = s0;
            sp[wm * 304 + col + 1]        = s1;
            sp[2432 + wm * 304 + col]     = q0;
            sp[2432 + wm * 304 + col + 1] = q1;
        }
    }
    __syncthreads();
    if (tid < DHP) {
        float s = 0.f, q = 0.f;
#pragma unroll
        for (int w = 0; w < 8; w++) { s += sp[w * 304 + tid]; q += sp[2432 + w * 304 + tid]; }
        g_part1s[(size_t)tid * G1_BLOCKS + blockIdx.x] = s;
        g_part1q[(size_t)tid * G1_BLOCKS + blockIdx.x] = q;
    }
}

// ---------------- reduce1: one block per column ----------------------------
__global__ void reduce1_kernel(const float* __restrict__ gamma1, const float* __restrict__ beta1) {
    __shared__ float ss[8], qq[8];
    const int col = blockIdx.x, t = threadIdx.x;   // 256 threads
    float s = g_part1s[(size_t)col * G1_BLOCKS + t] + g_part1s[(size_t)col * G1_BLOCKS + t + 256];
    float q = g_part1q[(size_t)col * G1_BLOCKS + t] + g_part1q[(size_t)col * G1_BLOCKS + t + 256];
#pragma unroll
    for (int o = 16; o > 0; o >>= 1) {
        s += __shfl_xor_sync(0xffffffffu, s, o);
        q += __shfl_xor_sync(0xffffffffu, q, o);
    }
    if ((t & 31) == 0) { ss[t >> 5] = s; qq[t >> 5] = q; }
    __syncthreads();
    if (t == 0) {
        float S = 0.f, Q = 0.f;
#pragma unroll
        for (int w = 0; w < 8; w++) { S += ss[w]; Q += qq[w]; }
        const float inv = 1.f / (float)B_ROWS;
        const float mean = S * inv;
        const float var  = Q * inv - mean * mean;
        float a = 0.f, b = 0.f;
        if (col < D_H) {
            a = gamma1[col] * rsqrtf(var + EPSV);
            b = beta1[col] - mean * a;
        }
        g_ab1[col] = a;
        g_ab1[DHP + col] = b;
    }
}

// ---------------- prep2: fold BN1 into W2 -----------------------------------
// c[j] = sum_k b[k]*sign(W2)[j][k];  then S'[j][k] = sign(W2)[j][k] * a[k] (in place)
__global__ void prep2_kernel() {
    const int tid = threadIdx.x;      // 320
    const int w = tid >> 5, lane = tid & 31;
    if (w < D_OUT) {
        float s = 0.f;
        for (int k = lane; k < D_H; k += 32)
            s += g_ab1[DHP + k] * __half2float(g_B2h[w * DHP + k]);
#pragma unroll
        for (int o = 16; o > 0; o >>= 1) s += __shfl_xor_sync(0xffffffffu, s, o);
        if (lane == 0) g_c2[w] = s;
    }
    if (lane == 1 && w < 6) g_c2[D_OUT + w] = 0.f;
    __syncthreads();
    for (int i = tid; i < 16 * DHP; i += 320) {
        const int k = i % DHP;
        g_B2h[i] = __float2half_rn(__half2float(g_B2h[i]) * g_ab1[k]);
    }
}

// ---------------- GEMM2: o = h @ S'^T + c, + BN2 partials -------------------
// Warp-autonomous: each of 8 warps owns 16 rows, cp.async depth-3 pipeline,
// no __syncthreads in the k-loop. A-path is a pure fp16 copy of h.
__global__ __launch_bounds__(256, 1) void gemm2_kernel(float* __restrict__ out) {
    __shared__ __align__(16) __half Bs2[16][312];     // S' tile (all K)
    __shared__ __align__(16) __half Astg[8 * 4 * 384];// 8 warps x 4 bufs x (16 rows x 24 halves)
    __shared__ float cs[16];
    __shared__ float ps[8][12], qs[8][12];

    const int tid = threadIdx.x, w = tid >> 5, lane = tid & 31;
    const int g = lane >> 2, tg = lane & 3;
    const int m0 = blockIdx.x * 128;
    const int row = lane & 15, hi = lane >> 4;

    for (int i = tid; i < 16 * 38; i += 256) {
        const int r = i / 38, c = (i % 38) * 8;
        *(uint4*)&Bs2[r][c] = *(const uint4*)(g_B2h + r * DHP + c);
    }
    if (tid < 16) cs[tid] = g_c2[tid];
    __syncthreads();

    const __half* src = g_h + (size_t)(m0 + w * 16 + row) * DHP + hi * 8;
    const uint32_t stgW   = smem_u32(Astg) + (uint32_t)w * 3072u;   // 4 bufs x 768B
    const uint32_t stgDst = stgW + (uint32_t)(row * 48 + hi * 16);
    const uint32_t ldsmA  = stgW + (uint32_t)((lane & 15) * 48 + (lane >> 4) * 16);

    float acc[2][4];
#pragma unroll
    for (int nt = 0; nt < 2; nt++)
#pragma unroll
        for (int e = 0; e < 4; e++) acc[nt][e] = 0.f;

#pragma unroll
    for (int p = 0; p < 3; p++) {       // depth-3 prologue
        CP_ASYNC16(stgDst + p * 768u, src + p * 16);
        CP_COMMIT();
    }
#pragma unroll
    for (int kb = 0; kb < 19; kb++) {
        const int buf = kb & 3;
        CP_WAIT2();
        __syncwarp();
        uint32_t a0, a1, a2, a3;
        LDSM_X4(a0, a1, a2, a3, ldsmA + buf * 768u);
        const uint32_t b00 = *(const uint32_t*)&Bs2[g]    [kb * 16 + tg * 2];
        const uint32_t b01 = *(const uint32_t*)&Bs2[g]    [kb * 16 + tg * 2 + 8];
        const uint32_t b10 = *(const uint32_t*)&Bs2[8 + g][kb * 16 + tg * 2];
        const uint32_t b11 = *(const uint32_t*)&Bs2[8 + g][kb * 16 + tg * 2 + 8];
        MMA16816(acc[0], a0, a1, a2, a3, b00, b01);
        MMA16816(acc[1], a0, a1, a2, a3, b10, b11);
        if (kb + 3 < 19) CP_ASYNC16(stgDst + ((kb + 3) & 3) * 768u, src + (kb + 3) * 16);
        CP_COMMIT();
    }

    // epilogue: add c, store, BN2 partials
    const int row0 = m0 + w * 16 + g;
    const float c00 = cs[tg * 2], c01 = cs[tg * 2 + 1];
    const float c10 = cs[8 + tg * 2], c11 = cs[9 + tg * 2];
    const float o00 = acc[0][0] + c00, o01 = acc[0][1] + c01;
    const float o02 = acc[0][2] + c00, o03 = acc[0][3] + c01;
    const float o10 = acc[1][0] + c10, o11 = acc[1][1] + c11;
    const float o12 = acc[1][2] + c10, o13 = acc[1][3] + c11;

    *(float2*)&out[(size_t)row0 * D_OUT + tg * 2]       = make_float2(o00, o01);
    *(float2*)&out[(size_t)(row0 + 8) * D_OUT + tg * 2] = make_float2(o02, o03);
    if (tg == 0) {
        *(float2*)&out[(size_t)row0 * D_OUT + 8]       = make_float2(o10, o11);
        *(float2*)&out[(size_t)(row0 + 8) * D_OUT + 8] = make_float2(o12, o13);
    }

    {
        float s0 = o00 + o02, s1 = o01 + o03;
        float q0 = o00 * o00 + o02 * o02, q1 = o01 * o01 + o03 * o03;
        float s2 = o10 + o12, s3 = o11 + o13;
        float q2 = o10 * o10 + o12 * o12, q3 = o11 * o11 + o13 * o13;
#pragma unroll
        for (int o = 4; o < 32; o <<= 1) {
            s0 += __shfl_xor_sync(0xffffffffu, s0, o);
            s1 += __shfl_xor_sync(0xffffffffu, s1, o);
            q0 += __shfl_xor_sync(0xffffffffu, q0, o);
            q1 += __shfl_xor_sync(0xffffffffu, q1, o);
            s2 += __shfl_xor_sync(0xffffffffu, s2, o);
            s3 += __shfl_xor_sync(0xffffffffu, s3, o);
            q2 += __shfl_xor_sync(0xffffffffu, q2, o);
            q3 += __shfl_xor_sync(0xffffffffu, q3, o);
        }
        if (g == 0) {
            const int c0 = tg * 2;
            ps[w][c0] = s0; ps[w][c0 + 1] = s1;
            qs[w][c0] = q0; qs[w][c0 + 1] = q1;
            if (tg == 0) {
                ps[w][8] = s2; ps[w][9] = s3;
                qs[w][8] = q2; qs[w][9] = q3;
            }
        }
    }
    __syncthreads();
    if (tid < D_OUT) {
        float s = 0.f, q = 0.f;
#pragma unroll
        for (int w2 = 0; w2 < 8; w2++) { s += ps[w2][tid]; q += qs[w2][tid]; }
        g_part2[blockIdx.x * 20 + tid] = s;
        g_part2[blockIdx.x * 20 + D_OUT + tid] = q;
    }
}

__global__ void reduce2_kernel(const float* __restrict__ gamma2, const float* __restrict__ beta2) {
    __shared__ float ss[256], qq[256];
    const int t = threadIdx.x, j = blockIdx.x;
    float s = 0.f, q = 0.f;
    for (int i = t; i < G2_BLOCKS; i += 256) {
        s += g_part2[i * 20 + j];
        q += g_part2[i * 20 + D_OUT + j];
    }
    ss[t] = s; qq[t] = q; __syncthreads();
    for (int o = 128; o > 0; o >>= 1) {
        if (t < o) { ss[t] += ss[t + o]; qq[t] += qq[t + o]; }
        __syncthreads();
    }
    if (t == 0) {
        const float inv = 1.f / (float)B_ROWS;
        const float mean = ss[0] * inv;
        const float var  = qq[0] * inv - mean * mean;
        const float a = gamma2[j] * rsqrtf(var + EPSV);
        g_ab2[j] = a;
        g_ab2[D_OUT + j] = beta2[j] - mean * a;
    }
}

__global__ void apply_kernel(float* __restrict__ out) {
    const int i = blockIdx.x * blockDim.x + threadIdx.x;
    if (i < B_ROWS * D_OUT) {
        const int j = i % D_OUT;
        out[i] = fmaf(out[i], g_ab2[j], g_ab2[D_OUT + j]);
    }
}

// ---------------- launch ---------------------------------------------------
extern "C" void kernel_launch(void* const* d_in, const int* in_sizes, int n_in,
                              void* d_out, int out_size) {
    const float* x      = (const float*)d_in[0];
    const float* W1     = (const float*)d_in[1];
    const float* gamma1 = (const float*)d_in[2];
    const float* beta1  = (const float*)d_in[3];
    const float* W2     = (const float*)d_in[4];
    const float* gamma2 = (const float*)d_in[5];
    const float* beta2  = (const float*)d_in[6];
    float* out = (float*)d_out;

    cudaFuncSetAttribute(gemm1_kernel, cudaFuncAttributeMaxDynamicSharedMemorySize, SMEM1_TOTAL);

    const int prepN = BNP * KP + 16 * DHP;
    prep_kernel<<<(prepN + 255) / 256, 256>>>(W1, W2);
    gemm1_kernel<<<G1_BLOCKS, 512, SMEM1_TOTAL>>>(x);
    reduce1_kernel<<<DHP, 256>>>(gamma1, beta1);
    prep2_kernel<<<1, 320>>>();
    gemm2_kernel<<<G2_BLOCKS, 256>>>(out);
    reduce2_kernel<<<D_OUT, 256>>>(gamma2, beta2);
    apply_kernel<<<(B_ROWS * D_OUT + 255) / 256, 256>>>(out);
}

// round 7
// speedup vs baseline: 1.1043x; 1.1043x over previous
#include <cuda_runtime.h>
#include <cuda_fp16.h>
#include <cstdint>

#define B_ROWS 65536
#define D_IN   784
#define KP     800      // K padded to 25 slabs of 32
#define D_H    300
#define DHP    304      // padded h width (stride)
#define BNP    320      // padded binarized-W1 rows
#define D_OUT  10
#define EPSV   1e-5f
#define G1_BLOCKS (B_ROWS / 128)   // 512
#define G2_BLOCKS (B_ROWS / 128)   // 512
#define NSLAB  25

// ---------------- scratch ---------------------------------------------------
__device__ __align__(16) __half g_Bh1[BNP * KP];            // sign(W1) fp16, zero-padded
__device__ __align__(16) __half g_B2h[16 * DHP];            // sign(W2) fp16 16x304
__device__ __align__(16) __half g_h[(size_t)B_ROWS * DHP];  // layer-1 pre-BN output
__device__ __align__(16) float  g_part1s[DHP * G1_BLOCKS];
__device__ __align__(16) float  g_part1q[DHP * G1_BLOCKS];
__device__ __align__(16) float  g_ab1[2 * DHP];
__device__ __align__(16) float  g_part2[G2_BLOCKS * 20];
__device__ __align__(16) float  g_ab2[2 * D_OUT];

__device__ __forceinline__ uint32_t smem_u32(const void* p) {
    uint32_t a;
    asm("{ .reg .u64 t; cvta.to.shared.u64 t, %1; cvt.u32.u64 %0, t; }" : "=r"(a) : "l"(p));
    return a;
}

#define MMA16816(acc, a0,a1,a2,a3, b0,b1)                                      \
    asm volatile(                                                              \
        "mma.sync.aligned.m16n8k16.row.col.f32.f16.f16.f32 "                   \
        "{%0,%1,%2,%3}, {%4,%5,%6,%7}, {%8,%9}, {%0,%1,%2,%3};\n"              \
        : "+f"(acc[0]), "+f"(acc[1]), "+f"(acc[2]), "+f"(acc[3])               \
        : "r"(a0), "r"(a1), "r"(a2), "r"(a3), "r"(b0), "r"(b1))

#define LDSM_X4(r0,r1,r2,r3, addr)                                             \
    asm volatile("ldmatrix.sync.aligned.m8n8.x4.shared.b16 {%0,%1,%2,%3}, [%4];" \
        : "=r"(r0), "=r"(r1), "=r"(r2), "=r"(r3) : "r"(addr))

#define CP_ASYNC16(dst, src)                                                   \
    asm volatile("cp.async.cg.shared.global [%0], [%1], 16;"                   \
        :: "r"(dst), "l"(src) : "memory")
#define CP_COMMIT() asm volatile("cp.async.commit_group;" ::: "memory")
#define CP_WAIT2()  asm volatile("cp.async.wait_group 2;" ::: "memory")

// ---------------- prep: binarize weights ----------------------------------
__global__ void prep_kernel(const float* __restrict__ W1, const float* __restrict__ W2) {
    int i = blockIdx.x * blockDim.x + threadIdx.x;
    const int n1 = BNP * KP;
    if (i < n1) {
        int n = i / KP, k = i - n * KP;
        float v = 0.f;
        if (n < D_H && k < D_IN) v = (W1[n * D_IN + k] >= 0.f) ? 1.f : -1.f;
        g_Bh1[i] = __float2half_rn(v);
    } else {
        int j = i - n1;
        if (j < 16 * DHP) {
            int r = j / DHP, c = j - r * DHP;
            float v = 0.f;
            if (r < D_OUT && c < D_H) v = (W2[r * D_H + c] >= 0.f) ? 1.f : -1.f;
            g_B2h[j] = __float2half_rn(v);
        }
    }
}

// ---------------- GEMM1 (round-5 winner): h = x @ sign(W1)^T + BN1 partials
// 128x320 tile, BK=32 double-buffered, 512 threads (16 warps 4m x 4n).
// ldmatrix.x4 fragment loads, one sync per slab. Row stride 80B.
#define SMEM1_TOTAL (20480 + 2 * 25600)

__global__ __launch_bounds__(512, 1) void gemm1_kernel(const float* __restrict__ x) {
    extern __shared__ __align__(128) char smem[];
    const uint32_t sb = smem_u32(smem);
    const int tid  = threadIdx.x;
    const int wid  = tid >> 5, lane = tid & 31;
    const int wm   = wid & 3,  wn   = wid >> 2;
    const int g    = lane >> 2, tg  = lane & 3;
    const int m0   = blockIdx.x * 128;

    float acc[2][10][4];
#pragma unroll
    for (int mt = 0; mt < 2; mt++)
#pragma unroll
        for (int nt = 0; nt < 10; nt++)
#pragma unroll
            for (int e = 0; e < 4; e++) acc[mt][nt][e] = 0.f;

    const uint32_t aAddr = sb + (uint32_t)((wm * 32 + (lane & 15)) * 80 + (lane >> 4) * 16);
    const uint32_t bAddr = sb + 20480u
        + (uint32_t)((wn * 80 + (lane & 7) + ((lane >> 4) << 3)) * 80 + ((lane >> 3) & 1) * 16);

    const float* xBase = x + (size_t)m0 * D_IN;
    float4 aR[2];
    uint4  bR[3];

#define LDG_SLAB(S)                                                              \
    do {                                                                         \
        const int kb = (S) * 32;                                                 \
        _Pragma("unroll")                                                        \
        for (int j = 0; j < 2; j++) {                                            \
            const int e = tid + 512 * j, row = e >> 3, c4 = (e & 7) * 4;         \
            aR[j] = (kb + c4 < D_IN)                                             \
                ? *(const float4*)(xBase + (size_t)row * D_IN + kb + c4)         \
                : make_float4(0.f, 0.f, 0.f, 0.f);                               \
        }                                                                        \
        _Pragma("unroll")                                                        \
        for (int j = 0; j < 2; j++) {                                            \
            const int u = tid + 512 * j;                                         \
            bR[j] = *(const uint4*)(g_Bh1 + (size_t)(u >> 2) * KP + kb + (u & 3) * 8); \
        }                                                                        \
        if (tid < 256) {                                                         \
            const int u = 1024 + tid;                                            \
            bR[2] = *(const uint4*)(g_Bh1 + (size_t)(u >> 2) * KP + kb + (u & 3) * 8); \
        }                                                                        \
    } while (0)

#define STS_SLAB(BUF)                                                            \
    do {                                                                         \
        const uint32_t aoff = (BUF) * 10240u;                                    \
        const uint32_t boff = 20480u + (BUF) * 25600u;                           \
        _Pragma("unroll")                                                        \
        for (int j = 0; j < 2; j++) {                                            \
            const int e = tid + 512 * j, row = e >> 3, c4 = (e & 7) * 4;         \
            __half2 h0 = __floats2half2_rn(aR[j].x, aR[j].y);                    \
            __half2 h1 = __floats2half2_rn(aR[j].z, aR[j].w);                    \
            uint2 v;                                                             \
            v.x = *(uint32_t*)&h0; v.y = *(uint32_t*)&h1;                        \
            *(uint2*)(smem + aoff + row * 80 + c4 * 2) = v;                      \
        }                                                                        \
        _Pragma("unroll")                                                        \
        for (int j = 0; j < 2; j++) {                                            \
            const int u = tid + 512 * j;                                         \
            *(uint4*)(smem + boff + (u >> 2) * 80 + (u & 3) * 16) = bR[j];       \
        }                                                                        \
        if (tid < 256) {                                                         \
            const int u = 1024 + tid;                                            \
            *(uint4*)(smem + boff + (u >> 2) * 80 + (u & 3) * 16) = bR[2];       \
        }                                                                        \
    } while (0)

#define COMPUTE_SLAB(BUF)                                                        \
    do {                                                                         \
        const uint32_t ab = aAddr + (BUF) * 10240u;                              \
        const uint32_t bb = bAddr + (BUF) * 25600u;                              \
        _Pragma("unroll")                                                        \
        for (int kk = 0; kk < 2; kk++) {                                         \
            uint32_t a0[4], a1[4];                                               \
            LDSM_X4(a0[0], a0[1], a0[2], a0[3], ab + kk * 32);                   \
            LDSM_X4(a1[0], a1[1], a1[2], a1[3], ab + 1280 + kk * 32);            \
            _Pragma("unroll")                                                    \
            for (int p = 0; p < 5; p++) {                                        \
                uint32_t b0, b1, b2, b3;                                         \
                LDSM_X4(b0, b1, b2, b3, bb + p * 1280 + kk * 32);                \
                MMA16816(acc[0][2 * p],     a0[0], a0[1], a0[2], a0[3], b0, b1); \
                MMA16816(acc[1][2 * p],     a1[0], a1[1], a1[2], a1[3], b0, b1); \
                MMA16816(acc[0][2 * p + 1], a0[0], a0[1], a0[2], a0[3], b2, b3); \
                MMA16816(acc[1][2 * p + 1], a1[0], a1[1], a1[2], a1[3], b2, b3); \
            }                                                                    \
        }                                                                        \
    } while (0)

    LDG_SLAB(0);
    STS_SLAB(0);
    __syncthreads();
    for (int s = 0; s < NSLAB; s++) {
        const int buf = s & 1;
        if (s < NSLAB - 1) LDG_SLAB(s + 1);
        COMPUTE_SLAB(buf);
        if (s < NSLAB - 1) STS_SLAB(buf ^ 1);
        __syncthreads();
    }
#undef LDG_SLAB
#undef STS_SLAB
#undef COMPUTE_SLAB

    // h stores (fp16)
#pragma unroll
    for (int mt = 0; mt < 2; mt++) {
        const int row0 = m0 + wm * 32 + mt * 16 + g;
#pragma unroll
        for (int nt = 0; nt < 10; nt++) {
            const int col = wn * 80 + nt * 8 + tg * 2;
            if (col < DHP) {
                *(__half2*)&g_h[(size_t)row0 * DHP + col]       = __floats2half2_rn(acc[mt][nt][0], acc[mt][nt][1]);
                *(__half2*)&g_h[(size_t)(row0 + 8) * DHP + col] = __floats2half2_rn(acc[mt][nt][2], acc[mt][nt][3]);
            }
        }
    }

    // fused BN1 column partials (deterministic)
    float* sp = (float*)smem;      // [4][320] sums, then [4][320] squares at +1280
#pragma unroll
    for (int nt = 0; nt < 10; nt++) {
        float s0 = 0.f, s1 = 0.f, q0 = 0.f, q1 = 0.f;
#pragma unroll
        for (int mt = 0; mt < 2; mt++) {
            const float v0 = acc[mt][nt][0], v1 = acc[mt][nt][1];
            const float v2 = acc[mt][nt][2], v3 = acc[mt][nt][3];
            s0 += v0 + v2;  s1 += v1 + v3;
            q0 += v0 * v0 + v2 * v2;  q1 += v1 * v1 + v3 * v3;
        }
#pragma unroll
        for (int o = 4; o < 32; o <<= 1) {
            s0 += __shfl_xor_sync(0xffffffffu, s0, o);
            s1 += __shfl_xor_sync(0xffffffffu, s1, o);
            q0 += __shfl_xor_sync(0xffffffffu, q0, o);
            q1 += __shfl_xor_sync(0xffffffffu, q1, o);
        }
        if (g == 0) {
            const int col = wn * 80 + nt * 8 + tg * 2;
            sp[wm * 320 + col]            = s0;
            sp[wm * 320 + col + 1]        = s1;
            sp[1280 + wm * 320 + col]     = q0;
            sp[1280 + wm * 320 + col + 1] = q1;
        }
    }
    __syncthreads();
    if (tid < DHP) {
        float s = 0.f, q = 0.f;
#pragma unroll
        for (int w = 0; w < 4; w++) { s += sp[w * 320 + tid]; q += sp[1280 + w * 320 + tid]; }
        g_part1s[(size_t)tid * G1_BLOCKS + blockIdx.x] = s;
        g_part1q[(size_t)tid * G1_BLOCKS + blockIdx.x] = q;
    }
}

// ---------------- reduce1: one block per column ----------------------------
__global__ void reduce1_kernel(const float* __restrict__ gamma1, const float* __restrict__ beta1) {
    __shared__ float ss[8], qq[8];
    const int col = blockIdx.x, t = threadIdx.x;   // 256 threads
    float s = g_part1s[(size_t)col * G1_BLOCKS + t] + g_part1s[(size_t)col * G1_BLOCKS + t + 256];
    float q = g_part1q[(size_t)col * G1_BLOCKS + t] + g_part1q[(size_t)col * G1_BLOCKS + t + 256];
#pragma unroll
    for (int o = 16; o > 0; o >>= 1) {
        s += __shfl_xor_sync(0xffffffffu, s, o);
        q += __shfl_xor_sync(0xffffffffu, q, o);
    }
    if ((t & 31) == 0) { ss[t >> 5] = s; qq[t >> 5] = q; }
    __syncthreads();
    if (t == 0) {
        float S = 0.f, Q = 0.f;
#pragma unroll
        for (int w = 0; w < 8; w++) { S += ss[w]; Q += qq[w]; }
        const float inv = 1.f / (float)B_ROWS;
        const float mean = S * inv;
        const float var  = Q * inv - mean * mean;
        float a = 0.f, b = 0.f;
        if (col < D_H) {
            a = gamma1[col] * rsqrtf(var + EPSV);
            b = beta1[col] - mean * a;
        }
        g_ab1[col] = a;
        g_ab1[DHP + col] = b;
    }
}

// ---------------- GEMM2: o = h @ (sign(W2) o a)^T + c, + BN2 partials ------
// BN1 folded into weights in the per-block preamble (no 1-block prep kernel):
//   S'[j][k] = sign(W2)[j][k] * a[k]  (fp16 round, staged to smem)
//   c[j]     = sum_k b[k] * sign(W2)[j][k]  (fp32 warp dots)
// k-loop: warp-autonomous cp.async depth-3 pipeline, no __syncthreads.
__global__ __launch_bounds__(256, 1) void gemm2_kernel(float* __restrict__ out) {
    __shared__ __align__(16) __half Bs2[16][312];      // S' tile (all K)
    __shared__ __align__(16) __half Astg[8 * 4 * 384]; // 8 warps x 4 bufs x (16 rows x 24 halves)
    __shared__ float cs[16];
    __shared__ float ps[8][12], qs[8][12];

    const int tid = threadIdx.x, w = tid >> 5, lane = tid & 31;
    const int g = lane >> 2, tg = lane & 3;
    const int m0 = blockIdx.x * 128;
    const int row = lane & 15, hi = lane >> 4;

    // stage S' = sign(W2) * a  (each thread: 19 halves = strided singles)
    for (int i = tid; i < 16 * DHP; i += 256) {
        const int r = i / DHP, k = i - r * DHP;
        Bs2[r][k] = __float2half_rn(__half2float(g_B2h[i]) * g_ab1[k]);
    }
    // c[j] = b . sign(W2)[j]  (warp w does j = w, and warps 0,1 also j = 8,9)
    for (int j = w; j < D_OUT; j += 8) {
        float s = 0.f;
        for (int k = lane; k < D_H; k += 32)
            s += g_ab1[DHP + k] * __half2float(g_B2h[j * DHP + k]);
#pragma unroll
        for (int o = 16; o > 0; o >>= 1) s += __shfl_xor_sync(0xffffffffu, s, o);
        if (lane == 0) cs[j] = s;
    }
    if (tid >= D_OUT && tid < 16) cs[tid] = 0.f;
    __syncthreads();

    const __half* src = g_h + (size_t)(m0 + w * 16 + row) * DHP + hi * 8;
    const uint32_t stgW   = smem_u32(Astg) + (uint32_t)w * 3072u;   // 4 bufs x 768B
    const uint32_t stgDst = stgW + (uint32_t)(row * 48 + hi * 16);
    const uint32_t ldsmA  = stgW + (uint32_t)((lane & 15) * 48 + (lane >> 4) * 16);

    float acc[2][4];
#pragma unroll
    for (int nt = 0; nt < 2; nt++)
#pragma unroll
        for (int e = 0; e < 4; e++) acc[nt][e] = 0.f;

#pragma unroll
    for (int p = 0; p < 3; p++) {       // depth-3 prologue
        CP_ASYNC16(stgDst + p * 768u, src + p * 16);
        CP_COMMIT();
    }
#pragma unroll
    for (int kb = 0; kb < 19; kb++) {
        const int buf = kb & 3;
        CP_WAIT2();
        __syncwarp();
        uint32_t a0, a1, a2, a3;
        LDSM_X4(a0, a1, a2, a3, ldsmA + buf * 768u);
        const uint32_t b00 = *(const uint32_t*)&Bs2[g]    [kb * 16 + tg * 2];
        const uint32_t b01 = *(const uint32_t*)&Bs2[g]    [kb * 16 + tg * 2 + 8];
        const uint32_t b10 = *(const uint32_t*)&Bs2[8 + g][kb * 16 + tg * 2];
        const uint32_t b11 = *(const uint32_t*)&Bs2[8 + g][kb * 16 + tg * 2 + 8];
        MMA16816(acc[0], a0, a1, a2, a3, b00, b01);
        MMA16816(acc[1], a0, a1, a2, a3, b10, b11);
        if (kb + 3 < 19) CP_ASYNC16(stgDst + ((kb + 3) & 3) * 768u, src + (kb + 3) * 16);
        CP_COMMIT();
    }

    // epilogue: add c, store, BN2 partials
    const int row0 = m0 + w * 16 + g;
    const float c00 = cs[tg * 2], c01 = cs[tg * 2 + 1];
    const float c10 = cs[8 + tg * 2], c11 = cs[9 + tg * 2];
    const float o00 = acc[0][0] + c00, o01 = acc[0][1] + c01;
    const float o02 = acc[0][2] + c00, o03 = acc[0][3] + c01;
    const float o10 = acc[1][0] + c10, o11 = acc[1][1] + c11;
    const float o12 = acc[1][2] + c10, o13 = acc[1][3] + c11;

    *(float2*)&out[(size_t)row0 * D_OUT + tg * 2]       = make_float2(o00, o01);
    *(float2*)&out[(size_t)(row0 + 8) * D_OUT + tg * 2] = make_float2(o02, o03);
    if (tg == 0) {
        *(float2*)&out[(size_t)row0 * D_OUT + 8]       = make_float2(o10, o11);
        *(float2*)&out[(size_t)(row0 + 8) * D_OUT + 8] = make_float2(o12, o13);
    }

    {
        float s0 = o00 + o02, s1 = o01 + o03;
        float q0 = o00 * o00 + o02 * o02, q1 = o01 * o01 + o03 * o03;
        float s2 = o10 + o12, s3 = o11 + o13;
        float q2 = o10 * o10 + o12 * o12, q3 = o11 * o11 + o13 * o13;
#pragma unroll
        for (int o = 4; o < 32; o <<= 1) {
            s0 += __shfl_xor_sync(0xffffffffu, s0, o);
            s1 += __shfl_xor_sync(0xffffffffu, s1, o);
            q0 += __shfl_xor_sync(0xffffffffu, q0, o);
            q1 += __shfl_xor_sync(0xffffffffu, q1, o);
            s2 += __shfl_xor_sync(0xffffffffu, s2, o);
            s3 += __shfl_xor_sync(0xffffffffu, s3, o);
            q2 += __shfl_xor_sync(0xffffffffu, q2, o);
            q3 += __shfl_xor_sync(0xffffffffu, q3, o);
        }
        if (g == 0) {
            const int c0 = tg * 2;
            ps[w][c0] = s0; ps[w][c0 + 1] = s1;
            qs[w][c0] = q0; qs[w][c0 + 1] = q1;
            if (tg == 0) {
                ps[w][8] = s2; ps[w][9] = s3;
                qs[w][8] = q2; qs[w][9] = q3;
            }
        }
    }
    __syncthreads();
    if (tid < D_OUT) {
        float s = 0.f, q = 0.f;
#pragma unroll
        for (int w2 = 0; w2 < 8; w2++) { s += ps[w2][tid]; q += qs[w2][tid]; }
        g_part2[blockIdx.x * 20 + tid] = s;
        g_part2[blockIdx.x * 20 + D_OUT + tid] = q;
    }
}

__global__ void reduce2_kernel(const float* __restrict__ gamma2, const float* __restrict__ beta2) {
    __shared__ float ss[256], qq[256];
    const int t = threadIdx.x, j = blockIdx.x;
    float s = 0.f, q = 0.f;
    for (int i = t; i < G2_BLOCKS; i += 256) {
        s += g_part2[i * 20 + j];
        q += g_part2[i * 20 + D_OUT + j];
    }
    ss[t] = s; qq[t] = q; __syncthreads();
    for (int o = 128; o > 0; o >>= 1) {
        if (t < o) { ss[t] += ss[t + o]; qq[t] += qq[t + o]; }
        __syncthreads();
    }
    if (t == 0) {
        const float inv = 1.f / (float)B_ROWS;
        const float mean = ss[0] * inv;
        const float var  = qq[0] * inv - mean * mean;
        const float a = gamma2[j] * rsqrtf(var + EPSV);
        g_ab2[j] = a;
        g_ab2[D_OUT + j] = beta2[j] - mean * a;
    }
}

__global__ void apply_kernel(float* __restrict__ out) {
    const int i = blockIdx.x * blockDim.x + threadIdx.x;
    if (i < B_ROWS * D_OUT) {
        const int j = i % D_OUT;
        out[i] = fmaf(out[i], g_ab2[j], g_ab2[D_OUT + j]);
    }
}

// ---------------- launch ---------------------------------------------------
extern "C" void kernel_launch(void* const* d_in, const int* in_sizes, int n_in,
                              void* d_out, int out_size) {
    const float* x      = (const float*)d_in[0];
    const float* W1     = (const float*)d_in[1];
    const float* gamma1 = (const float*)d_in[2];
    const float* beta1  = (const float*)d_in[3];
    const float* W2     = (const float*)d_in[4];
    const float* gamma2 = (const float*)d_in[5];
    const float* beta2  = (const float*)d_in[6];
    float* out = (float*)d_out;

    cudaFuncSetAttribute(gemm1_kernel, cudaFuncAttributeMaxDynamicSharedMemorySize, SMEM1_TOTAL);

    const int prepN = BNP * KP + 16 * DHP;
    prep_kernel<<<(prepN + 255) / 256, 256>>>(W1, W2);
    gemm1_kernel<<<G1_BLOCKS, 512, SMEM1_TOTAL>>>(x);
    reduce1_kernel<<<DHP, 256>>>(gamma1, beta1);
    gemm2_kernel<<<G2_BLOCKS, 256>>>(out);
    reduce2_kernel<<<D_OUT, 256>>>(gamma2, beta2);
    apply_kernel<<<(B_ROWS * D_OUT + 255) / 256, 256>>>(out);
}